// round 7
// baseline (speedup 1.0000x reference)
#include <cuda_runtime.h>
#include <cstdint>

#define VOCAB 100000
#define EMBED 64
#define BATCH 1024
#define SEQ   50
#define KIDS  20
#define NPOS  (BATCH * SEQ)   // 51200

// Scratch: W transposed to [VOCAB, EMBED] so each id gather is 256B contiguous.
// 100000 * 64 * 4B = 25.6 MB (fits in L2).
__device__ float g_WT[(size_t)VOCAB * EMBED];

// ---------------------------------------------------------------------------
// Kernel 1: tiled transpose  W[E=64, V=100000] (row-major)  ->  WT[V, E]
// 32x32 tiles via padded smem; V % 32 == 0 and E % 32 == 0, so no bounds.
// ---------------------------------------------------------------------------
__global__ __launch_bounds__(256) void transpose_W_kernel(const float* __restrict__ W) {
    __shared__ float tile[32][33];

    const int tx = threadIdx.x;        // 0..31
    const int ty = threadIdx.y;        // 0..7
    const int v0 = blockIdx.x * 32;    // vocab tile base
    const int e0 = blockIdx.y * 32;    // embed tile base (0 or 32)

    // Read: coalesced along V (inner dim of W)
    #pragma unroll
    for (int j = 0; j < 32; j += 8) {
        tile[ty + j][tx] = W[(size_t)(e0 + ty + j) * VOCAB + (v0 + tx)];
    }
    __syncthreads();

    // Write: coalesced along E (inner dim of WT)
    #pragma unroll
    for (int j = 0; j < 32; j += 8) {
        g_WT[(size_t)(v0 + ty + j) * EMBED + (e0 + tx)] = tile[tx][ty + j];
    }
}

// ---------------------------------------------------------------------------
// Kernel 2: embedding-bag gather. One warp per (b,s) position.
// Lane l owns output elements [2l, 2l+1] (float2). Ids broadcast via shuffle.
// 20 independent 256B-contiguous warp loads per position -> high MLP.
// ---------------------------------------------------------------------------
__global__ __launch_bounds__(256) void gather_sum_kernel(
    const int*   __restrict__ ids,    // [NPOS, KIDS]
    const float* __restrict__ bias,   // [EMBED]
    float*       __restrict__ out)    // [NPOS, EMBED]
{
    const int warp = threadIdx.x >> 5;
    const int lane = threadIdx.x & 31;
    const int pos  = blockIdx.x * 8 + warp;
    if (pos >= NPOS) return;

    // Lanes 0..19 load the 20 ids for this position (coalesced 80B read).
    const int* idp = ids + (size_t)pos * KIDS;
    int my_id = (lane < KIDS) ? __ldg(idp + lane) : 0;

    float2 acc = make_float2(0.f, 0.f);

    #pragma unroll
    for (int k = 0; k < KIDS; ++k) {
        int id = __shfl_sync(0xffffffffu, my_id, k);
        const float2 w = *reinterpret_cast<const float2*>(
            g_WT + (size_t)id * EMBED + lane * 2);
        acc.x += w.x;
        acc.y += w.y;
    }

    const float2 bb = *reinterpret_cast<const float2*>(bias + lane * 2);
    acc.x += bb.x;
    acc.y += bb.y;

    *reinterpret_cast<float2*>(out + (size_t)pos * EMBED + lane * 2) = acc;
}

// ---------------------------------------------------------------------------
// Launch
// inputs (metadata order): 0 = content_input int32 [B,S,K], 1 = W f32 [E,V],
//                          2 = b f32 [E].   output: f32 [B,S,E]
// ---------------------------------------------------------------------------
extern "C" void kernel_launch(void* const* d_in, const int* in_sizes, int n_in,
                              void* d_out, int out_size) {
    const int*   ids  = (const int*)d_in[0];
    const float* W    = (const float*)d_in[1];
    const float* bias = (const float*)d_in[2];
    float*       out  = (float*)d_out;

    // Transpose: grid (V/32, E/32) = (3125, 2), block (32, 8)
    dim3 tb(32, 8);
    dim3 tg(VOCAB / 32, EMBED / 32);
    transpose_W_kernel<<<tg, tb>>>(W);

    // Gather: 8 warps/block, one warp per position
    const int blocks = (NPOS + 7) / 8;   // 6400
    gather_sum_kernel<<<blocks, 256>>>(ids, bias, out);
}